// round 2
// baseline (speedup 1.0000x reference)
#include <cuda_runtime.h>
#include <cstdint>

#define OMEGA_W 0.9f

#define N0 2048
#define N1 1024
#define N2 512
#define N3 256

// Scratch (device globals — no allocation allowed).
__device__ float g_u0b[N0 * N0];
__device__ float g_u1a[N1 * N1];
__device__ float g_u1b[N1 * N1];
__device__ float g_r1[N1 * N1];
__device__ float g_u2a[N2 * N2];
__device__ float g_u2b[N2 * N2];
__device__ float g_r2[N2 * N2];

// ---------------------------------------------------------------------------
// First Jacobi sweep with u == 0:  u_new = omega * rhs / diag
// diag = -((cx+cx_w)+(cy+cy_s))*ih2 - 1   (always <= -1, never zero)
// ---------------------------------------------------------------------------
__global__ void jacobi0_kernel(const float* __restrict__ rhs,
                               const float* __restrict__ cx,
                               const float* __restrict__ cy,
                               float* __restrict__ un, int n, float ih2) {
    int i = blockIdx.x * blockDim.x + threadIdx.x;
    int j = blockIdx.y * blockDim.y + threadIdx.y;
    if (i >= n || j >= n) return;
    int idx = j * n + i;
    float cxe = cx[idx];
    float cyn = cy[idx];
    float cxw = (i > 0) ? cx[idx - 1] : 0.0f;
    float cys = (j > 0) ? cy[idx - n] : 0.0f;
    float diag = -((cxe + cxw) + (cyn + cys)) * ih2 - 1.0f;
    un[idx] = OMEGA_W * rhs[idx] / diag;
}

// ---------------------------------------------------------------------------
// One weighted-Jacobi sweep (diagonal computed inline — no inv array).
// ---------------------------------------------------------------------------
__global__ void jacobi_kernel(const float* __restrict__ u,
                              const float* __restrict__ rhs,
                              const float* __restrict__ cx,
                              const float* __restrict__ cy,
                              float* __restrict__ un, int n, float ih2) {
    int i = blockIdx.x * blockDim.x + threadIdx.x;
    int j = blockIdx.y * blockDim.y + threadIdx.y;
    if (i >= n || j >= n) return;
    int idx = j * n + i;

    float um = u[idx];
    float ue = (i + 1 < n) ? u[idx + 1] : 0.0f;
    float uw = (i > 0) ? u[idx - 1] : 0.0f;
    float uN = (j + 1 < n) ? u[idx + n] : 0.0f;
    float uS = (j > 0) ? u[idx - n] : 0.0f;

    float cxe = cx[idx];
    float cxw = (i > 0) ? cx[idx - 1] : 0.0f;
    float cyn = cy[idx];
    float cys = (j > 0) ? cy[idx - n] : 0.0f;

    float lap = (cxe * (ue - um) - cxw * (um - uw)) * ih2 +
                (cyn * (uN - um) - cys * (um - uS)) * ih2;
    float Au = lap - um;               // LAM = 1
    float r = rhs[idx] - Au;
    float diag = -((cxe + cxw) + (cyn + cys)) * ih2 - 1.0f;
    un[idx] = um + OMEGA_W * r / diag;
}

// ---------------------------------------------------------------------------
// Residual at one fine point (global memory).
// ---------------------------------------------------------------------------
__device__ __forceinline__ float resid_pt(const float* __restrict__ u,
                                          const float* __restrict__ rhs,
                                          const float* __restrict__ cx,
                                          const float* __restrict__ cy,
                                          int j, int i, int n, float ih2) {
    int idx = j * n + i;
    float um = u[idx];
    float ue = (i + 1 < n) ? u[idx + 1] : 0.0f;
    float uw = (i > 0) ? u[idx - 1] : 0.0f;
    float uN = (j + 1 < n) ? u[idx + n] : 0.0f;
    float uS = (j > 0) ? u[idx - n] : 0.0f;
    float cxe = cx[idx];
    float cxw = (i > 0) ? cx[idx - 1] : 0.0f;
    float cyn = cy[idx];
    float cys = (j > 0) ? cy[idx - n] : 0.0f;
    float lap = (cxe * (ue - um) - cxw * (um - uw)) * ih2 +
                (cyn * (uN - um) - cys * (um - uS)) * ih2;
    return rhs[idx] - (lap - um);
}

// ---------------------------------------------------------------------------
// Fused residual + restriction: one thread per COARSE point.
// ---------------------------------------------------------------------------
__global__ void resid_restrict_kernel(const float* __restrict__ u,
                                      const float* __restrict__ rhs,
                                      const float* __restrict__ cx,
                                      const float* __restrict__ cy,
                                      float* __restrict__ rc, int n, float ih2) {
    int nc = n >> 1;
    int ic = blockIdx.x * blockDim.x + threadIdx.x;
    int jc = blockIdx.y * blockDim.y + threadIdx.y;
    if (ic >= nc || jc >= nc) return;
    int jf = 2 * jc, ifi = 2 * ic;
    float s = resid_pt(u, rhs, cx, cy, jf, ifi, n, ih2) +
              resid_pt(u, rhs, cx, cy, jf + 1, ifi, n, ih2) +
              resid_pt(u, rhs, cx, cy, jf, ifi + 1, n, ih2) +
              resid_pt(u, rhs, cx, cy, jf + 1, ifi + 1, n, ih2);
    rc[jc * nc + ic] = 0.25f * s;
}

// ---------------------------------------------------------------------------
// Fused prolongation + correction: u_fine += P(e_coarse).
// ---------------------------------------------------------------------------
__global__ void prolong_add_kernel(float* __restrict__ u,
                                   const float* __restrict__ e, int nf) {
    int nc = nf >> 1;
    int i = blockIdx.x * blockDim.x + threadIdx.x;
    int j = blockIdx.y * blockDim.y + threadIdx.y;
    if (i >= nf || j >= nf) return;

    int jc = j >> 1, dj = j & 1;
    int ic = i >> 1, di = i & 1;
    int sj = dj ? 1 : -1;
    int si = di ? 1 : -1;

    bool bi = ((unsigned)(ic + si) < (unsigned)nc);
    bool bj = ((unsigned)(jc + sj) < (unsigned)nc);

    float vc = e[jc * nc + ic];
    float vsi = bi ? e[jc * nc + ic + si] : 0.0f;
    float vsj = bj ? e[(jc + sj) * nc + ic] : 0.0f;
    float vd = (bi && bj) ? e[(jc + sj) * nc + ic + si] : 0.0f;

    float den = 9.0f + 3.0f * (bi ? 1.0f : 0.0f) + 3.0f * (bj ? 1.0f : 0.0f) +
                ((bi && bj) ? 1.0f : 0.0f);
    float w = 9.0f * vc + 3.0f * vsi + 3.0f * vsj + vd;
    u[j * nf + i] += w / den;
}

// ===========================================================================
// Fused level-3 solver: one 8-CTA cluster kernel.
//   restrict(u2,r2 -> r3) + coefficient build + 22 Jacobi sweeps in SMEM
//   (DSMEM halos + cluster barriers) + prolong-add back into u2.
// CTA rank r owns coarse rows [32r, 32r+32) of the 256x256 level-3 grid.
// ===========================================================================
#define L3_ROWS 32

__device__ __forceinline__ unsigned cl_rank() {
    unsigned r;
    asm("mov.u32 %0, %%cluster_ctarank;" : "=r"(r));
    return r;
}
__device__ __forceinline__ void cl_sync() {
    asm volatile("barrier.cluster.arrive.aligned;" ::: "memory");
    asm volatile("barrier.cluster.wait.aligned;" ::: "memory");
}
__device__ __forceinline__ float dsmem_ldf(const float* p, unsigned rank) {
    unsigned laddr = (unsigned)__cvta_generic_to_shared((void*)p);
    unsigned raddr;
    float v;
    asm volatile("mapa.shared::cluster.u32 %0, %1, %2;"
                 : "=r"(raddr) : "r"(laddr), "r"(rank));
    asm volatile("ld.shared::cluster.f32 %0, [%1];"
                 : "=f"(v) : "r"(raddr) : "memory");
    return v;
}

__global__ void __cluster_dims__(8, 1, 1) __launch_bounds__(256, 1)
l3_fused_kernel(float* __restrict__ u2, const float* __restrict__ r2,
                const float* __restrict__ cx2, const float* __restrict__ cy2,
                const float* __restrict__ cx3, const float* __restrict__ cy3) {
    extern __shared__ float sm[];
    float* ua  = sm;                 // 32x256
    float* ub  = sm + 8192;
    float* ae  = sm + 2 * 8192;     // omega*inv*ih2*cx_e
    float* aw  = sm + 3 * 8192;
    float* an  = sm + 4 * 8192;
    float* as_ = sm + 5 * 8192;
    float* bb  = sm + 6 * 8192;     // omega*inv*r3
    float* halo = sm + 7 * 8192;    // 2 rows of 256 (prolong halos)

    const unsigned rank = cl_rank();
    const int i = threadIdx.x;               // column 0..255
    const int row0 = (int)rank * L3_ROWS;
    const float ih2_3 = 0.015625f;           // 1/(8^2)
    const float ih2_2 = 0.0625f;             // 1/(4^2)

    // ---- setup: restrict L2 residual + build Jacobi coefficients ----
    for (int j = 0; j < L3_ROWS; ++j) {
        int gj = row0 + j;
        float rr = 0.0f;
#pragma unroll
        for (int dj = 0; dj < 2; ++dj) {
            int fj = 2 * gj + dj;
#pragma unroll
            for (int di = 0; di < 2; ++di) {
                int fi = 2 * i + di;
                rr += resid_pt(u2, r2, cx2, cy2, fj, fi, N2, ih2_2);
            }
        }
        rr *= 0.25f;

        int cidx = gj * N3 + i;
        float cxe = cx3[cidx];
        float cxw = (i > 0) ? cx3[cidx - 1] : 0.0f;
        float cyn = cy3[cidx];
        float cys = (gj > 0) ? cy3[cidx - N3] : 0.0f;
        float inv = 1.0f / (-((cxe + cxw) + (cyn + cys)) * ih2_3 - 1.0f);
        float w = OMEGA_W * inv * ih2_3;
        int ji = j * N3 + i;
        ae[ji] = w * cxe;
        aw[ji] = w * cxw;
        an[ji] = w * cyn;
        as_[ji] = w * cys;
        float b = OMEGA_W * inv * rr;
        bb[ji] = b;
        ua[ji] = b;  // sweep 0: u starts at 0 -> u = omega*inv*r
    }

    // ---- 21 more sweeps (22 total), SMEM-resident, DSMEM halos ----
    float* src = ua;
    float* dst = ub;
    for (int k = 0; k < 21; ++k) {
        cl_sync();  // neighbor's src is complete
        float us_r = (rank > 0) ? dsmem_ldf(&src[(L3_ROWS - 1) * N3 + i], rank - 1) : 0.0f;
        float un_r = (rank < 7) ? dsmem_ldf(&src[i], rank + 1) : 0.0f;
        float us = us_r;
        float um = src[i];
#pragma unroll 4
        for (int j = 0; j < L3_ROWS; ++j) {
            int ji = j * N3 + i;
            float un = (j + 1 < L3_ROWS) ? src[ji + N3] : un_r;
            float ue = (i + 1 < N3) ? src[ji + 1] : 0.0f;
            float uw = (i > 0) ? src[ji - 1] : 0.0f;
            dst[ji] = (1.0f - OMEGA_W) * um + bb[ji] -
                      (ae[ji] * ue + aw[ji] * uw + an[ji] * un + as_[ji] * us);
            us = um;
            um = un;
        }
        float* t = src; src = dst; dst = t;
    }
    // final solution in src

    // ---- prolongation halos (coarse rows row0-1 and row0+32) ----
    cl_sync();
    halo[i]      = (rank > 0) ? dsmem_ldf(&src[(L3_ROWS - 1) * N3 + i], rank - 1) : 0.0f;
    halo[N3 + i] = (rank < 7) ? dsmem_ldf(&src[i], rank + 1) : 0.0f;
    __syncthreads();

    // ---- prolong + add into u2 (fine rows [64r, 64r+64) of 512 grid) ----
    for (int jf = 64 * (int)rank; jf < 64 * (int)rank + 64; ++jf) {
        int jc = jf >> 1, dj = jf & 1;
        int sj = dj ? 1 : -1;
        int jl = jc - row0;       // local coarse row 0..31
        int jsl = jl + sj;        // -1..32
        bool bj = ((unsigned)(jc + sj) < (unsigned)N3);
        for (int ii = i; ii < N2; ii += 256) {
            int ic = ii >> 1, di = ii & 1;
            int si = di ? 1 : -1;
            bool bi = ((unsigned)(ic + si) < (unsigned)N3);
            float vc = src[jl * N3 + ic];
            float vsi = bi ? src[jl * N3 + ic + si] : 0.0f;
            float vsj, vd;
            if (jsl >= 0 && jsl < L3_ROWS) {
                vsj = bj ? src[jsl * N3 + ic] : 0.0f;
                vd = (bi && bj) ? src[jsl * N3 + ic + si] : 0.0f;
            } else {
                const float* hrow = (jsl < 0) ? halo : (halo + N3);
                vsj = bj ? hrow[ic] : 0.0f;
                vd = (bi && bj) ? hrow[ic + si] : 0.0f;
            }
            float den = 9.0f + 3.0f * (bi ? 1.0f : 0.0f) + 3.0f * (bj ? 1.0f : 0.0f) +
                        ((bi && bj) ? 1.0f : 0.0f);
            float w = 9.0f * vc + 3.0f * vsi + 3.0f * vsj + vd;
            u2[jf * N2 + ii] += w / den;
        }
    }
}

// ---------------------------------------------------------------------------
// Host driver
// ---------------------------------------------------------------------------
extern "C" void kernel_launch(void* const* d_in, const int* in_sizes, int n_in,
                              void* d_out, int out_size) {
    const float* cx[4];
    const float* cy[4];
    const float* rhs;
    if (in_sizes[2] == in_sizes[0]) {
        // dict order: mask0,cx0,cy0, mask1,... , rhs
        for (int l = 0; l < 4; ++l) {
            cx[l] = (const float*)d_in[3 * l + 1];
            cy[l] = (const float*)d_in[3 * l + 2];
        }
        rhs = (const float*)d_in[12];
    } else {
        // signature order: rhs, mask0..3, cx0..3, cy0..3
        rhs = (const float*)d_in[0];
        for (int l = 0; l < 4; ++l) {
            cx[l] = (const float*)d_in[5 + l];
            cy[l] = (const float*)d_in[9 + l];
        }
    }

    float *u0a = (float*)d_out, *u0b;
    float *u1a, *u1b, *r1;
    float *u2a, *u2b, *r2;
    cudaGetSymbolAddress((void**)&u0b, g_u0b);
    cudaGetSymbolAddress((void**)&u1a, g_u1a);
    cudaGetSymbolAddress((void**)&u1b, g_u1b);
    cudaGetSymbolAddress((void**)&r1, g_r1);
    cudaGetSymbolAddress((void**)&u2a, g_u2a);
    cudaGetSymbolAddress((void**)&u2b, g_u2b);
    cudaGetSymbolAddress((void**)&r2, g_r2);

    const float ih2_0 = 1.0f, ih2_1 = 0.25f, ih2_2 = 0.0625f;

    dim3 blk(32, 8);
    dim3 g0(N0 / 32, N0 / 8);
    dim3 g1(N1 / 32, N1 / 8);
    dim3 g2(N2 / 32, N2 / 8);

    const int l3_smem = (7 * 8192 + 512) * sizeof(float);  // 231,424 B
    cudaFuncSetAttribute(l3_fused_kernel,
                         cudaFuncAttributeMaxDynamicSharedMemorySize, l3_smem);

    for (int cyc = 0; cyc < 2; ++cyc) {
        // ----- level 0: pre-smooth (2) -----
        if (cyc == 0) {
            jacobi0_kernel<<<g0, blk>>>(rhs, cx[0], cy[0], u0b, N0, ih2_0);
        } else {
            jacobi_kernel<<<g0, blk>>>(u0a, rhs, cx[0], cy[0], u0b, N0, ih2_0);
        }
        jacobi_kernel<<<g0, blk>>>(u0b, rhs, cx[0], cy[0], u0a, N0, ih2_0);
        resid_restrict_kernel<<<g1, blk>>>(u0a, rhs, cx[0], cy[0], r1, N0, ih2_0);

        // ----- level 1: pre-smooth (2) -----
        jacobi0_kernel<<<g1, blk>>>(r1, cx[1], cy[1], u1b, N1, ih2_1);
        jacobi_kernel<<<g1, blk>>>(u1b, r1, cx[1], cy[1], u1a, N1, ih2_1);
        resid_restrict_kernel<<<g2, blk>>>(u1a, r1, cx[1], cy[1], r2, N1, ih2_1);

        // ----- level 2: pre-smooth (2) -----
        jacobi0_kernel<<<g2, blk>>>(r2, cx[2], cy[2], u2b, N2, ih2_2);
        jacobi_kernel<<<g2, blk>>>(u2b, r2, cx[2], cy[2], u2a, N2, ih2_2);

        // ----- fused: restrict->level3 (22 sweeps)->prolong into u2a -----
        l3_fused_kernel<<<8, 256, l3_smem>>>(u2a, r2, cx[2], cy[2], cx[3], cy[3]);

        // ----- level 2: post-smooth (2) -----
        jacobi_kernel<<<g2, blk>>>(u2a, r2, cx[2], cy[2], u2b, N2, ih2_2);
        jacobi_kernel<<<g2, blk>>>(u2b, r2, cx[2], cy[2], u2a, N2, ih2_2);

        // ----- level 1: correct + post-smooth (2) -----
        prolong_add_kernel<<<g1, blk>>>(u1a, u2a, N1);
        jacobi_kernel<<<g1, blk>>>(u1a, r1, cx[1], cy[1], u1b, N1, ih2_1);
        jacobi_kernel<<<g1, blk>>>(u1b, r1, cx[1], cy[1], u1a, N1, ih2_1);

        // ----- level 0: correct + post-smooth (2) -----
        prolong_add_kernel<<<g0, blk>>>(u0a, u1a, N0);
        jacobi_kernel<<<g0, blk>>>(u0a, rhs, cx[0], cy[0], u0b, N0, ih2_0);
        jacobi_kernel<<<g0, blk>>>(u0b, rhs, cx[0], cy[0], u0a, N0, ih2_0);
    }
}

// round 3
// speedup vs baseline: 1.7889x; 1.7889x over previous
#include <cuda_runtime.h>
#include <cstdint>

#define OMEGA_W 0.9f

#define N0 2048
#define N1 1024
#define N2 512
#define N3 256

// Scratch (device globals — no allocation allowed).
__device__ float g_u0b[N0 * N0];
__device__ float g_u1a[N1 * N1];
__device__ float g_u1b[N1 * N1];
__device__ float g_r1[N1 * N1];
__device__ float g_u2a[N2 * N2];
__device__ float g_u2b[N2 * N2];
__device__ float g_r2[N2 * N2];
__device__ float g_u3a[N3 * N3];
__device__ float g_u3b[N3 * N3];
__device__ float g_r3[N3 * N3];

// ---------------------------------------------------------------------------
// Plain weighted-Jacobi sweep (global memory, inline diagonal).
// ---------------------------------------------------------------------------
__global__ void jacobi_kernel(const float* __restrict__ u,
                              const float* __restrict__ rhs,
                              const float* __restrict__ cx,
                              const float* __restrict__ cy,
                              float* __restrict__ un, int n, float ih2) {
    int i = blockIdx.x * blockDim.x + threadIdx.x;
    int j = blockIdx.y * blockDim.y + threadIdx.y;
    int idx = j * n + i;

    float um = u[idx];
    float ue = (i + 1 < n) ? u[idx + 1] : 0.0f;
    float uw = (i > 0) ? u[idx - 1] : 0.0f;
    float uN = (j + 1 < n) ? u[idx + n] : 0.0f;
    float uS = (j > 0) ? u[idx - n] : 0.0f;

    float cxe = cx[idx];
    float cxw = (i > 0) ? cx[idx - 1] : 0.0f;
    float cyn = cy[idx];
    float cys = (j > 0) ? cy[idx - n] : 0.0f;

    float lap = (cxe * (ue - um) - cxw * (um - uw)) * ih2 +
                (cyn * (uN - um) - cys * (um - uS)) * ih2;
    float r = rhs[idx] - (lap - um);
    float diag = -((cxe + cxw) + (cyn + cys)) * ih2 - 1.0f;
    un[idx] = um + OMEGA_W * r / diag;
}

// ---------------------------------------------------------------------------
// Device helper: one Jacobi update at a global point (global-memory reads).
// ---------------------------------------------------------------------------
__device__ __forceinline__ float jac_pt(const float* __restrict__ u,
                                        const float* __restrict__ rhs,
                                        const float* __restrict__ cx,
                                        const float* __restrict__ cy,
                                        int gy, int gx, int n, float ih2) {
    int idx = gy * n + gx;
    float um = u[idx];
    float ue = (gx + 1 < n) ? u[idx + 1] : 0.0f;
    float uw = (gx > 0) ? u[idx - 1] : 0.0f;
    float uN = (gy + 1 < n) ? u[idx + n] : 0.0f;
    float uS = (gy > 0) ? u[idx - n] : 0.0f;
    float cxe = cx[idx];
    float cxw = (gx > 0) ? cx[idx - 1] : 0.0f;
    float cyn = cy[idx];
    float cys = (gy > 0) ? cy[idx - n] : 0.0f;
    float lap = (cxe * (ue - um) - cxw * (um - uw)) * ih2 +
                (cyn * (uN - um) - cys * (um - uS)) * ih2;
    float r = rhs[idx] - (lap - um);
    float diag = -((cxe + cxw) + (cyn + cys)) * ih2 - 1.0f;
    return um + OMEGA_W * r / diag;
}

// ===========================================================================
// jrr: fused {sweep Jacobi} + {residual of result} + {restrict}.
// Block (32,8). Fine tile 64x16 per CTA (thread owns 2x2), coarse out 32x8.
// ===========================================================================
__global__ __launch_bounds__(256)
void jrr_kernel(const float* __restrict__ u,
                const float* __restrict__ rhs,
                const float* __restrict__ cx,
                const float* __restrict__ cy,
                float* __restrict__ udst,
                float* __restrict__ rc, int n, float ih2) {
    __shared__ float su[18 * 66];
    const int tx = threadIdx.x, ty = threadIdx.y;
    const int tid = ty * 32 + tx;
    const int bx0 = blockIdx.x * 64, by0 = blockIdx.y * 16;

    for (int sp = tid; sp < 18 * 66; sp += 256) {
        int py = sp / 66, px = sp % 66;
        int gy = by0 + py - 1, gx = bx0 + px - 1;
        float v = 0.0f;
        if ((unsigned)gy < (unsigned)n && (unsigned)gx < (unsigned)n)
            v = jac_pt(u, rhs, cx, cy, gy, gx, n, ih2);
        su[sp] = v;
    }
    __syncthreads();

    const int gx0 = bx0 + 2 * tx, gy0 = by0 + 2 * ty;
    const int lx0 = 2 * tx + 1, ly0 = 2 * ty + 1;

    *reinterpret_cast<float2*>(&udst[gy0 * n + gx0]) =
        make_float2(su[ly0 * 66 + lx0], su[ly0 * 66 + lx0 + 1]);
    *reinterpret_cast<float2*>(&udst[(gy0 + 1) * n + gx0]) =
        make_float2(su[(ly0 + 1) * 66 + lx0], su[(ly0 + 1) * 66 + lx0 + 1]);

    float s = 0.0f;
#pragma unroll
    for (int dy = 0; dy < 2; ++dy) {
#pragma unroll
        for (int dx = 0; dx < 2; ++dx) {
            int fy = gy0 + dy, fx = gx0 + dx;
            int ly = ly0 + dy, lx = lx0 + dx;
            float um = su[ly * 66 + lx];
            float ue = su[ly * 66 + lx + 1];
            float uw = su[ly * 66 + lx - 1];
            float uN = su[(ly + 1) * 66 + lx];
            float uS = su[(ly - 1) * 66 + lx];
            int idx = fy * n + fx;
            float cxe = cx[idx];
            float cxw = (fx > 0) ? cx[idx - 1] : 0.0f;
            float cyn = cy[idx];
            float cys = (fy > 0) ? cy[idx - n] : 0.0f;
            float lap = (cxe * (ue - um) - cxw * (um - uw)) * ih2 +
                        (cyn * (uN - um) - cys * (um - uS)) * ih2;
            s += rhs[idx] - (lap - um);
        }
    }
    int nc = n >> 1;
    rc[(blockIdx.y * 8 + ty) * nc + blockIdx.x * 32 + tx] = 0.25f * s;
}

// ===========================================================================
// jrr0: u_before == 0 -> sweep-1 is local (omega*inv*rhs). Fuses
// jacobi0 + jacobi + residual + restrict into one kernel.
// ===========================================================================
__global__ __launch_bounds__(256)
void jrr0_kernel(const float* __restrict__ rhs,
                 const float* __restrict__ cx,
                 const float* __restrict__ cy,
                 float* __restrict__ udst,
                 float* __restrict__ rc, int n, float ih2) {
    __shared__ float s1[20 * 68];
    __shared__ float su[18 * 66];
    const int tx = threadIdx.x, ty = threadIdx.y;
    const int tid = ty * 32 + tx;
    const int bx0 = blockIdx.x * 64, by0 = blockIdx.y * 16;

    for (int sp = tid; sp < 20 * 68; sp += 256) {
        int py = sp / 68, px = sp % 68;
        int gy = by0 + py - 2, gx = bx0 + px - 2;
        float v = 0.0f;
        if ((unsigned)gy < (unsigned)n && (unsigned)gx < (unsigned)n) {
            int idx = gy * n + gx;
            float cxe = cx[idx];
            float cxw = (gx > 0) ? cx[idx - 1] : 0.0f;
            float cyn = cy[idx];
            float cys = (gy > 0) ? cy[idx - n] : 0.0f;
            float diag = -((cxe + cxw) + (cyn + cys)) * ih2 - 1.0f;
            v = OMEGA_W * rhs[idx] / diag;
        }
        s1[sp] = v;
    }
    __syncthreads();

    for (int sp = tid; sp < 18 * 66; sp += 256) {
        int py = sp / 66, px = sp % 66;
        int gy = by0 + py - 1, gx = bx0 + px - 1;
        float v = 0.0f;
        if ((unsigned)gy < (unsigned)n && (unsigned)gx < (unsigned)n) {
            int l1 = (py + 1) * 68 + (px + 1);
            float um = s1[l1];
            float ue = s1[l1 + 1];
            float uw = s1[l1 - 1];
            float uN = s1[l1 + 68];
            float uS = s1[l1 - 68];
            int idx = gy * n + gx;
            float cxe = cx[idx];
            float cxw = (gx > 0) ? cx[idx - 1] : 0.0f;
            float cyn = cy[idx];
            float cys = (gy > 0) ? cy[idx - n] : 0.0f;
            float lap = (cxe * (ue - um) - cxw * (um - uw)) * ih2 +
                        (cyn * (uN - um) - cys * (um - uS)) * ih2;
            float r = rhs[idx] - (lap - um);
            float diag = -((cxe + cxw) + (cyn + cys)) * ih2 - 1.0f;
            v = um + OMEGA_W * r / diag;
        }
        su[sp] = v;
    }
    __syncthreads();

    const int gx0 = bx0 + 2 * tx, gy0 = by0 + 2 * ty;
    const int lx0 = 2 * tx + 1, ly0 = 2 * ty + 1;

    *reinterpret_cast<float2*>(&udst[gy0 * n + gx0]) =
        make_float2(su[ly0 * 66 + lx0], su[ly0 * 66 + lx0 + 1]);
    *reinterpret_cast<float2*>(&udst[(gy0 + 1) * n + gx0]) =
        make_float2(su[(ly0 + 1) * 66 + lx0], su[(ly0 + 1) * 66 + lx0 + 1]);

    float s = 0.0f;
#pragma unroll
    for (int dy = 0; dy < 2; ++dy) {
#pragma unroll
        for (int dx = 0; dx < 2; ++dx) {
            int fy = gy0 + dy, fx = gx0 + dx;
            int ly = ly0 + dy, lx = lx0 + dx;
            float um = su[ly * 66 + lx];
            float ue = su[ly * 66 + lx + 1];
            float uw = su[ly * 66 + lx - 1];
            float uN = su[(ly + 1) * 66 + lx];
            float uS = su[(ly - 1) * 66 + lx];
            int idx = fy * n + fx;
            float cxe = cx[idx];
            float cxw = (fx > 0) ? cx[idx - 1] : 0.0f;
            float cyn = cy[idx];
            float cys = (fy > 0) ? cy[idx - n] : 0.0f;
            float lap = (cxe * (ue - um) - cxw * (um - uw)) * ih2 +
                        (cyn * (uN - um) - cys * (um - uS)) * ih2;
            s += rhs[idx] - (lap - um);
        }
    }
    int nc = n >> 1;
    rc[(blockIdx.y * 8 + ty) * nc + blockIdx.x * 32 + tx] = 0.25f * s;
}

// ===========================================================================
// pj: fused {u += prolong(e)} + {one Jacobi sweep}.
// ===========================================================================
__global__ __launch_bounds__(256)
void pj_kernel(const float* __restrict__ u,
               const float* __restrict__ e,
               const float* __restrict__ rhs,
               const float* __restrict__ cx,
               const float* __restrict__ cy,
               float* __restrict__ udst, int n, float ih2) {
    __shared__ float su[18 * 66];
    const int tx = threadIdx.x, ty = threadIdx.y;
    const int tid = ty * 32 + tx;
    const int bx0 = blockIdx.x * 64, by0 = blockIdx.y * 16;
    const int ncc = n >> 1;

    for (int sp = tid; sp < 18 * 66; sp += 256) {
        int py = sp / 66, px = sp % 66;
        int gy = by0 + py - 1, gx = bx0 + px - 1;
        float v = 0.0f;
        if ((unsigned)gy < (unsigned)n && (unsigned)gx < (unsigned)n) {
            int jc = gy >> 1, dj = gy & 1;
            int ic = gx >> 1, di = gx & 1;
            int sj = dj ? 1 : -1;
            int si = di ? 1 : -1;
            bool bi = ((unsigned)(ic + si) < (unsigned)ncc);
            bool bj = ((unsigned)(jc + sj) < (unsigned)ncc);
            float vc = e[jc * ncc + ic];
            float vsi = bi ? e[jc * ncc + ic + si] : 0.0f;
            float vsj = bj ? e[(jc + sj) * ncc + ic] : 0.0f;
            float vd = (bi && bj) ? e[(jc + sj) * ncc + ic + si] : 0.0f;
            float den = 9.0f + 3.0f * (bi ? 1.0f : 0.0f) +
                        3.0f * (bj ? 1.0f : 0.0f) + ((bi && bj) ? 1.0f : 0.0f);
            v = u[gy * n + gx] + (9.0f * vc + 3.0f * vsi + 3.0f * vsj + vd) / den;
        }
        su[sp] = v;
    }
    __syncthreads();

    const int gx0 = bx0 + 2 * tx, gy0 = by0 + 2 * ty;
    const int lx0 = 2 * tx + 1, ly0 = 2 * ty + 1;
    float out[2][2];
#pragma unroll
    for (int dy = 0; dy < 2; ++dy) {
#pragma unroll
        for (int dx = 0; dx < 2; ++dx) {
            int fy = gy0 + dy, fx = gx0 + dx;
            int ly = ly0 + dy, lx = lx0 + dx;
            float um = su[ly * 66 + lx];
            float ue = su[ly * 66 + lx + 1];
            float uw = su[ly * 66 + lx - 1];
            float uN = su[(ly + 1) * 66 + lx];
            float uS = su[(ly - 1) * 66 + lx];
            int idx = fy * n + fx;
            float cxe = cx[idx];
            float cxw = (fx > 0) ? cx[idx - 1] : 0.0f;
            float cyn = cy[idx];
            float cys = (fy > 0) ? cy[idx - n] : 0.0f;
            float lap = (cxe * (ue - um) - cxw * (um - uw)) * ih2 +
                        (cyn * (uN - um) - cys * (um - uS)) * ih2;
            float r = rhs[idx] - (lap - um);
            float diag = -((cxe + cxw) + (cyn + cys)) * ih2 - 1.0f;
            out[dy][dx] = um + OMEGA_W * r / diag;
        }
    }
    *reinterpret_cast<float2*>(&udst[gy0 * n + gx0]) = make_float2(out[0][0], out[0][1]);
    *reinterpret_cast<float2*>(&udst[(gy0 + 1) * n + gx0]) = make_float2(out[1][0], out[1][1]);
}

// ===========================================================================
// L3 temporal-blocked multi-sweep: 64 CTAs, each owns 32x32 with halo 6.
// ===========================================================================
#define L3H 6
#define L3W 44
#define L3PTS (L3W * L3W)

__global__ __launch_bounds__(256)
void l3_sweeps_kernel(const float* __restrict__ uin,
                      const float* __restrict__ r3,
                      const float* __restrict__ cx3,
                      const float* __restrict__ cy3,
                      float* __restrict__ uout, int nswp, int zero_start) {
    extern __shared__ float sm[];
    float* u0 = sm;
    float* u1 = sm + L3PTS;
    float* ae = sm + 2 * L3PTS;
    float* aw = sm + 3 * L3PTS;
    float* an = sm + 4 * L3PTS;
    float* as_ = sm + 5 * L3PTS;
    float* bb = sm + 6 * L3PTS;

    const int tid = threadIdx.x;
    const int gx0 = blockIdx.x * 32 - L3H;
    const int gy0 = blockIdx.y * 32 - L3H;
    const float ih2 = 0.015625f;

    for (int sp = tid; sp < L3PTS; sp += 256) {
        int py = sp / L3W, px = sp % L3W;
        int gy = gy0 + py, gx = gx0 + px;
        float uu = 0.0f, ce = 0.0f, cw = 0.0f, cn = 0.0f, cs = 0.0f, b = 0.0f;
        if ((unsigned)gy < (unsigned)N3 && (unsigned)gx < (unsigned)N3) {
            int idx = gy * N3 + gx;
            if (!zero_start) uu = uin[idx];
            float cxe = cx3[idx];
            float cxw = (gx > 0) ? cx3[idx - 1] : 0.0f;
            float cyn = cy3[idx];
            float cys = (gy > 0) ? cy3[idx - N3] : 0.0f;
            float inv = 1.0f / (-((cxe + cxw) + (cyn + cys)) * ih2 - 1.0f);
            float w = OMEGA_W * inv;
            float wi = w * ih2;
            ce = wi * cxe; cw = wi * cxw; cn = wi * cyn; cs = wi * cys;
            b = w * r3[idx];
        }
        u0[sp] = uu; ae[sp] = ce; aw[sp] = cw; an[sp] = cn; as_[sp] = cs; bb[sp] = b;
    }
    __syncthreads();

    float* src = u0;
    float* dst = u1;
    for (int k = 0; k < nswp; ++k) {
        int lo = k + 1, hi = L3W - 1 - k;
        int width = hi - lo;
        int npts = width * width;
        for (int q = tid; q < npts; q += 256) {
            int py = lo + q / width, px = lo + q % width;
            int p = py * L3W + px;
            float um = src[p];
            dst[p] = (1.0f - OMEGA_W) * um + bb[p] -
                     (ae[p] * src[p + 1] + aw[p] * src[p - 1] +
                      an[p] * src[p + L3W] + as_[p] * src[p - L3W]);
        }
        __syncthreads();
        float* t = src; src = dst; dst = t;
    }

    for (int q = tid; q < 1024; q += 256) {
        int py = L3H + q / 32, px = L3H + q % 32;
        uout[(gy0 + py) * N3 + (gx0 + px)] = src[py * L3W + px];
    }
}

// ---------------------------------------------------------------------------
// Host driver
// ---------------------------------------------------------------------------
extern "C" void kernel_launch(void* const* d_in, const int* in_sizes, int n_in,
                              void* d_out, int out_size) {
    const float* cx[4];
    const float* cy[4];
    const float* rhs;
    if (in_sizes[2] == in_sizes[0]) {
        for (int l = 0; l < 4; ++l) {
            cx[l] = (const float*)d_in[3 * l + 1];
            cy[l] = (const float*)d_in[3 * l + 2];
        }
        rhs = (const float*)d_in[12];
    } else {
        rhs = (const float*)d_in[0];
        for (int l = 0; l < 4; ++l) {
            cx[l] = (const float*)d_in[5 + l];
            cy[l] = (const float*)d_in[9 + l];
        }
    }

    float *u0a = (float*)d_out, *u0b;
    float *u1a, *u1b, *r1;
    float *u2a, *u2b, *r2;
    float *u3a, *u3b, *r3;
    cudaGetSymbolAddress((void**)&u0b, g_u0b);
    cudaGetSymbolAddress((void**)&u1a, g_u1a);
    cudaGetSymbolAddress((void**)&u1b, g_u1b);
    cudaGetSymbolAddress((void**)&r1, g_r1);
    cudaGetSymbolAddress((void**)&u2a, g_u2a);
    cudaGetSymbolAddress((void**)&u2b, g_u2b);
    cudaGetSymbolAddress((void**)&r2, g_r2);
    cudaGetSymbolAddress((void**)&u3a, g_u3a);
    cudaGetSymbolAddress((void**)&u3b, g_u3b);
    cudaGetSymbolAddress((void**)&r3, g_r3);

    const float ih2_0 = 1.0f, ih2_1 = 0.25f, ih2_2 = 0.0625f;

    dim3 blk(32, 8);
    dim3 j0(N0 / 32, N0 / 8);
    dim3 t0(N0 / 64, N0 / 16);
    dim3 t1(N1 / 64, N1 / 16);
    dim3 t2(N2 / 64, N2 / 16);
    dim3 g3(8, 8);

    const int l3_smem = 7 * L3PTS * sizeof(float);  // 54,208 B
    cudaFuncSetAttribute(l3_sweeps_kernel,
                         cudaFuncAttributeMaxDynamicSharedMemorySize, l3_smem);

    for (int cyc = 0; cyc < 2; ++cyc) {
        // ----- level 0: pre-smooth (2) + residual + restrict -> r1, u in u0a
        if (cyc == 0) {
            jrr0_kernel<<<t0, blk>>>(rhs, cx[0], cy[0], u0a, r1, N0, ih2_0);
        } else {
            jacobi_kernel<<<j0, blk>>>(u0a, rhs, cx[0], cy[0], u0b, N0, ih2_0);
            jrr_kernel<<<t0, blk>>>(u0b, rhs, cx[0], cy[0], u0a, r1, N0, ih2_0);
        }

        // ----- level 1: pre (2, from zero) + residual + restrict -> r2
        jrr0_kernel<<<t1, blk>>>(r1, cx[1], cy[1], u1a, r2, N1, ih2_1);

        // ----- level 2: pre (2, from zero) + residual + restrict -> r3
        jrr0_kernel<<<t2, blk>>>(r2, cx[2], cy[2], u2a, r3, N2, ih2_2);

        // ----- level 3: 22 sweeps = 6+6+6+4 temporal-blocked launches
        l3_sweeps_kernel<<<g3, 256, l3_smem>>>(u3b, r3, cx[3], cy[3], u3a, 6, 1);
        l3_sweeps_kernel<<<g3, 256, l3_smem>>>(u3a, r3, cx[3], cy[3], u3b, 6, 0);
        l3_sweeps_kernel<<<g3, 256, l3_smem>>>(u3b, r3, cx[3], cy[3], u3a, 6, 0);
        l3_sweeps_kernel<<<g3, 256, l3_smem>>>(u3a, r3, cx[3], cy[3], u3b, 4, 0);

        // ----- level 2: correct + post (2)
        pj_kernel<<<t2, blk>>>(u2a, u3b, r2, cx[2], cy[2], u2b, N2, ih2_2);
        jacobi_kernel<<<dim3(N2 / 32, N2 / 8), blk>>>(u2b, r2, cx[2], cy[2], u2a, N2, ih2_2);

        // ----- level 1: correct + post (2)
        pj_kernel<<<t1, blk>>>(u1a, u2a, r1, cx[1], cy[1], u1b, N1, ih2_1);
        jacobi_kernel<<<dim3(N1 / 32, N1 / 8), blk>>>(u1b, r1, cx[1], cy[1], u1a, N1, ih2_1);

        // ----- level 0: correct + post (2)
        pj_kernel<<<t0, blk>>>(u0a, u1a, rhs, cx[0], cy[0], u0b, N0, ih2_0);
        jacobi_kernel<<<j0, blk>>>(u0b, rhs, cx[0], cy[0], u0a, N0, ih2_0);
        // final u in u0a == d_out
    }
}

// round 4
// speedup vs baseline: 1.8970x; 1.0604x over previous
#include <cuda_runtime.h>
#include <cstdint>

#define OMEGA_W 0.9f

#define N0 2048
#define N1 1024
#define N2 512
#define N3 256

// Scratch (device globals — no allocation allowed).
__device__ float g_u0b[N0 * N0];
__device__ float g_u0c[N0 * N0];
__device__ float g_u1a[N1 * N1];
__device__ float g_u1b[N1 * N1];
__device__ float g_r1[N1 * N1];
__device__ float g_u2a[N2 * N2];
__device__ float g_u2b[N2 * N2];
__device__ float g_r2[N2 * N2];
__device__ float g_u3a[N3 * N3];
__device__ float g_u3b[N3 * N3];
__device__ float g_r3[N3 * N3];

// ---------------------------------------------------------------------------
// One Jacobi update at a global point (global-memory reads).
// ---------------------------------------------------------------------------
__device__ __forceinline__ float jac_pt(const float* __restrict__ u,
                                        const float* __restrict__ rhs,
                                        const float* __restrict__ cx,
                                        const float* __restrict__ cy,
                                        int gy, int gx, int n, float ih2) {
    int idx = gy * n + gx;
    float um = u[idx];
    float ue = (gx + 1 < n) ? u[idx + 1] : 0.0f;
    float uw = (gx > 0) ? u[idx - 1] : 0.0f;
    float uN = (gy + 1 < n) ? u[idx + n] : 0.0f;
    float uS = (gy > 0) ? u[idx - n] : 0.0f;
    float cxe = cx[idx];
    float cxw = (gx > 0) ? cx[idx - 1] : 0.0f;
    float cyn = cy[idx];
    float cys = (gy > 0) ? cy[idx - n] : 0.0f;
    float lap = (cxe * (ue - um) - cxw * (um - uw)) * ih2 +
                (cyn * (uN - um) - cys * (um - uS)) * ih2;
    float r = rhs[idx] - (lap - um);
    float diag = -((cxe + cxw) + (cyn + cys)) * ih2 - 1.0f;
    return um + OMEGA_W * r / diag;
}

// ---------------------------------------------------------------------------
// One Jacobi update from an SMEM u-tile (coeffs from global).
// sm is indexed with row stride `stride`, point at sm[ly*stride+lx].
// ---------------------------------------------------------------------------
__device__ __forceinline__ float jac_sm(const float* __restrict__ sm,
                                        int ly, int lx, int stride,
                                        const float* __restrict__ rhs,
                                        const float* __restrict__ cx,
                                        const float* __restrict__ cy,
                                        int gy, int gx, int n, float ih2) {
    int lp = ly * stride + lx;
    float um = sm[lp];
    float ue = sm[lp + 1];
    float uw = sm[lp - 1];
    float uN = sm[lp + stride];
    float uS = sm[lp - stride];
    int idx = gy * n + gx;
    float cxe = cx[idx];
    float cxw = (gx > 0) ? cx[idx - 1] : 0.0f;
    float cyn = cy[idx];
    float cys = (gy > 0) ? cy[idx - n] : 0.0f;
    float lap = (cxe * (ue - um) - cxw * (um - uw)) * ih2 +
                (cyn * (uN - um) - cys * (um - uS)) * ih2;
    float r = rhs[idx] - (lap - um);
    float diag = -((cxe + cxw) + (cyn + cys)) * ih2 - 1.0f;
    return um + OMEGA_W * r / diag;
}

// ---------------------------------------------------------------------------
// Residual from an SMEM u-tile.
// ---------------------------------------------------------------------------
__device__ __forceinline__ float resid_sm(const float* __restrict__ sm,
                                          int ly, int lx, int stride,
                                          const float* __restrict__ rhs,
                                          const float* __restrict__ cx,
                                          const float* __restrict__ cy,
                                          int gy, int gx, int n, float ih2) {
    int lp = ly * stride + lx;
    float um = sm[lp];
    float ue = sm[lp + 1];
    float uw = sm[lp - 1];
    float uN = sm[lp + stride];
    float uS = sm[lp - stride];
    int idx = gy * n + gx;
    float cxe = cx[idx];
    float cxw = (gx > 0) ? cx[idx - 1] : 0.0f;
    float cyn = cy[idx];
    float cys = (gy > 0) ? cy[idx - n] : 0.0f;
    float lap = (cxe * (ue - um) - cxw * (um - uw)) * ih2 +
                (cyn * (uN - um) - cys * (um - uS)) * ih2;
    return rhs[idx] - (lap - um);
}

// ===========================================================================
// jrr0: u==0 start. sweep1 (local) -> sweep2 -> residual -> restrict.
// Block (32,8); fine tile 64x16 (thread owns 2x2); coarse out 32x8.
// ===========================================================================
__global__ __launch_bounds__(256)
void jrr0_kernel(const float* __restrict__ rhs,
                 const float* __restrict__ cx,
                 const float* __restrict__ cy,
                 float* __restrict__ udst,
                 float* __restrict__ rc, int n, float ih2) {
    __shared__ float s1[20 * 68];
    __shared__ float su[18 * 66];
    const int tx = threadIdx.x, ty = threadIdx.y;
    const int tid = ty * 32 + tx;
    const int bx0 = blockIdx.x * 64, by0 = blockIdx.y * 16;

    for (int sp = tid; sp < 20 * 68; sp += 256) {
        int py = sp / 68, px = sp % 68;
        int gy = by0 + py - 2, gx = bx0 + px - 2;
        float v = 0.0f;
        if ((unsigned)gy < (unsigned)n && (unsigned)gx < (unsigned)n) {
            int idx = gy * n + gx;
            float cxe = cx[idx];
            float cxw = (gx > 0) ? cx[idx - 1] : 0.0f;
            float cyn = cy[idx];
            float cys = (gy > 0) ? cy[idx - n] : 0.0f;
            float diag = -((cxe + cxw) + (cyn + cys)) * ih2 - 1.0f;
            v = OMEGA_W * rhs[idx] / diag;
        }
        s1[sp] = v;
    }
    __syncthreads();

    for (int sp = tid; sp < 18 * 66; sp += 256) {
        int py = sp / 66, px = sp % 66;
        int gy = by0 + py - 1, gx = bx0 + px - 1;
        float v = 0.0f;
        if ((unsigned)gy < (unsigned)n && (unsigned)gx < (unsigned)n)
            v = jac_sm(s1, py + 1, px + 1, 68, rhs, cx, cy, gy, gx, n, ih2);
        su[sp] = v;
    }
    __syncthreads();

    const int gx0 = bx0 + 2 * tx, gy0 = by0 + 2 * ty;
    const int lx0 = 2 * tx + 1, ly0 = 2 * ty + 1;

    *reinterpret_cast<float2*>(&udst[gy0 * n + gx0]) =
        make_float2(su[ly0 * 66 + lx0], su[ly0 * 66 + lx0 + 1]);
    *reinterpret_cast<float2*>(&udst[(gy0 + 1) * n + gx0]) =
        make_float2(su[(ly0 + 1) * 66 + lx0], su[(ly0 + 1) * 66 + lx0 + 1]);

    float s = resid_sm(su, ly0, lx0, 66, rhs, cx, cy, gy0, gx0, n, ih2) +
              resid_sm(su, ly0, lx0 + 1, 66, rhs, cx, cy, gy0, gx0 + 1, n, ih2) +
              resid_sm(su, ly0 + 1, lx0, 66, rhs, cx, cy, gy0 + 1, gx0, n, ih2) +
              resid_sm(su, ly0 + 1, lx0 + 1, 66, rhs, cx, cy, gy0 + 1, gx0 + 1, n, ih2);
    int nc = n >> 1;
    rc[(blockIdx.y * 8 + ty) * nc + blockIdx.x * 32 + tx] = 0.25f * s;
}

// ===========================================================================
// jrr2: nonzero u start. sweep1 (global u, halo2) -> sweep2 -> residual ->
// restrict. Replaces jacobi + jrr.
// ===========================================================================
__global__ __launch_bounds__(256)
void jrr2_kernel(const float* __restrict__ u,
                 const float* __restrict__ rhs,
                 const float* __restrict__ cx,
                 const float* __restrict__ cy,
                 float* __restrict__ udst,
                 float* __restrict__ rc, int n, float ih2) {
    __shared__ float s1[20 * 68];
    __shared__ float su[18 * 66];
    const int tx = threadIdx.x, ty = threadIdx.y;
    const int tid = ty * 32 + tx;
    const int bx0 = blockIdx.x * 64, by0 = blockIdx.y * 16;

    for (int sp = tid; sp < 20 * 68; sp += 256) {
        int py = sp / 68, px = sp % 68;
        int gy = by0 + py - 2, gx = bx0 + px - 2;
        float v = 0.0f;
        if ((unsigned)gy < (unsigned)n && (unsigned)gx < (unsigned)n)
            v = jac_pt(u, rhs, cx, cy, gy, gx, n, ih2);
        s1[sp] = v;
    }
    __syncthreads();

    for (int sp = tid; sp < 18 * 66; sp += 256) {
        int py = sp / 66, px = sp % 66;
        int gy = by0 + py - 1, gx = bx0 + px - 1;
        float v = 0.0f;
        if ((unsigned)gy < (unsigned)n && (unsigned)gx < (unsigned)n)
            v = jac_sm(s1, py + 1, px + 1, 68, rhs, cx, cy, gy, gx, n, ih2);
        su[sp] = v;
    }
    __syncthreads();

    const int gx0 = bx0 + 2 * tx, gy0 = by0 + 2 * ty;
    const int lx0 = 2 * tx + 1, ly0 = 2 * ty + 1;

    *reinterpret_cast<float2*>(&udst[gy0 * n + gx0]) =
        make_float2(su[ly0 * 66 + lx0], su[ly0 * 66 + lx0 + 1]);
    *reinterpret_cast<float2*>(&udst[(gy0 + 1) * n + gx0]) =
        make_float2(su[(ly0 + 1) * 66 + lx0], su[(ly0 + 1) * 66 + lx0 + 1]);

    float s = resid_sm(su, ly0, lx0, 66, rhs, cx, cy, gy0, gx0, n, ih2) +
              resid_sm(su, ly0, lx0 + 1, 66, rhs, cx, cy, gy0, gx0 + 1, n, ih2) +
              resid_sm(su, ly0 + 1, lx0, 66, rhs, cx, cy, gy0 + 1, gx0, n, ih2) +
              resid_sm(su, ly0 + 1, lx0 + 1, 66, rhs, cx, cy, gy0 + 1, gx0 + 1, n, ih2);
    int nc = n >> 1;
    rc[(blockIdx.y * 8 + ty) * nc + blockIdx.x * 32 + tx] = 0.25f * s;
}

// ===========================================================================
// pjj: fused {u += prolong(e)} + TWO Jacobi sweeps (complete post-smooth).
// Phase 0: corrected u on halo-2 (20x68). Phase 1: sweep1 on halo-1 (18x66).
// Phase 2: sweep2 on owned 64x16 + store.
// ===========================================================================
__global__ __launch_bounds__(256)
void pjj_kernel(const float* __restrict__ u,
                const float* __restrict__ e,
                const float* __restrict__ rhs,
                const float* __restrict__ cx,
                const float* __restrict__ cy,
                float* __restrict__ udst, int n, float ih2) {
    __shared__ float s1[20 * 68];
    __shared__ float su[18 * 66];
    const int tx = threadIdx.x, ty = threadIdx.y;
    const int tid = ty * 32 + tx;
    const int bx0 = blockIdx.x * 64, by0 = blockIdx.y * 16;
    const int ncc = n >> 1;

    for (int sp = tid; sp < 20 * 68; sp += 256) {
        int py = sp / 68, px = sp % 68;
        int gy = by0 + py - 2, gx = bx0 + px - 2;
        float v = 0.0f;
        if ((unsigned)gy < (unsigned)n && (unsigned)gx < (unsigned)n) {
            int jc = gy >> 1, dj = gy & 1;
            int ic = gx >> 1, di = gx & 1;
            int sj = dj ? 1 : -1;
            int si = di ? 1 : -1;
            bool bi = ((unsigned)(ic + si) < (unsigned)ncc);
            bool bj = ((unsigned)(jc + sj) < (unsigned)ncc);
            float vc = e[jc * ncc + ic];
            float vsi = bi ? e[jc * ncc + ic + si] : 0.0f;
            float vsj = bj ? e[(jc + sj) * ncc + ic] : 0.0f;
            float vd = (bi && bj) ? e[(jc + sj) * ncc + ic + si] : 0.0f;
            float den = 9.0f + 3.0f * (bi ? 1.0f : 0.0f) +
                        3.0f * (bj ? 1.0f : 0.0f) + ((bi && bj) ? 1.0f : 0.0f);
            v = u[gy * n + gx] + (9.0f * vc + 3.0f * vsi + 3.0f * vsj + vd) / den;
        }
        s1[sp] = v;
    }
    __syncthreads();

    for (int sp = tid; sp < 18 * 66; sp += 256) {
        int py = sp / 66, px = sp % 66;
        int gy = by0 + py - 1, gx = bx0 + px - 1;
        float v = 0.0f;
        if ((unsigned)gy < (unsigned)n && (unsigned)gx < (unsigned)n)
            v = jac_sm(s1, py + 1, px + 1, 68, rhs, cx, cy, gy, gx, n, ih2);
        su[sp] = v;
    }
    __syncthreads();

    const int gx0 = bx0 + 2 * tx, gy0 = by0 + 2 * ty;
    const int lx0 = 2 * tx + 1, ly0 = 2 * ty + 1;
    float o00 = jac_sm(su, ly0, lx0, 66, rhs, cx, cy, gy0, gx0, n, ih2);
    float o01 = jac_sm(su, ly0, lx0 + 1, 66, rhs, cx, cy, gy0, gx0 + 1, n, ih2);
    float o10 = jac_sm(su, ly0 + 1, lx0, 66, rhs, cx, cy, gy0 + 1, gx0, n, ih2);
    float o11 = jac_sm(su, ly0 + 1, lx0 + 1, 66, rhs, cx, cy, gy0 + 1, gx0 + 1, n, ih2);
    *reinterpret_cast<float2*>(&udst[gy0 * n + gx0]) = make_float2(o00, o01);
    *reinterpret_cast<float2*>(&udst[(gy0 + 1) * n + gx0]) = make_float2(o10, o11);
}

// ===========================================================================
// L3 temporal-blocked multi-sweep: 64 CTAs x 512 threads, tile 32x32,
// halo 11 -> 11 sweeps per launch (22 sweeps = 2 launches).
// Fixed thread->point mapping, no runtime division in the sweep loop.
// Full interior recomputed each sweep; owned [11,43)^2 stays exact.
// ===========================================================================
#define L3H 11
#define L3W 54              // 32 + 2*11
#define L3WS 56             // padded row stride
#define L3PTS (L3W * L3WS)

__global__ __launch_bounds__(512)
void l3_sweeps_kernel(const float* __restrict__ uin,
                      const float* __restrict__ r3,
                      const float* __restrict__ cx3,
                      const float* __restrict__ cy3,
                      float* __restrict__ uout, int zero_start) {
    extern __shared__ float sm[];
    float* ua = sm;
    float* ub = sm + L3PTS;
    float* ae = sm + 2 * L3PTS;
    float* aw = sm + 3 * L3PTS;
    float* an = sm + 4 * L3PTS;
    float* as_ = sm + 5 * L3PTS;
    float* bb = sm + 6 * L3PTS;

    const int tx = threadIdx.x, ty = threadIdx.y;   // (32,16)
    const int tid = ty * 32 + tx;
    const int gx0 = blockIdx.x * 32 - L3H;
    const int gy0 = blockIdx.y * 32 - L3H;
    const float ih2 = 0.015625f;

    // ---- load: coefficients + initial u on 54x54 (clipped; pad cols unread)
    for (int sp = tid; sp < L3W * L3W; sp += 512) {
        int py = sp / L3W, px = sp % L3W;
        int p = py * L3WS + px;
        int gy = gy0 + py, gx = gx0 + px;
        float uu = 0.0f, ce = 0.0f, cw = 0.0f, cn = 0.0f, cs = 0.0f, b = 0.0f;
        if ((unsigned)gy < (unsigned)N3 && (unsigned)gx < (unsigned)N3) {
            int idx = gy * N3 + gx;
            if (!zero_start) uu = uin[idx];
            float cxe = cx3[idx];
            float cxw = (gx > 0) ? cx3[idx - 1] : 0.0f;
            float cyn = cy3[idx];
            float cys = (gy > 0) ? cy3[idx - N3] : 0.0f;
            float inv = 1.0f / (-((cxe + cxw) + (cyn + cys)) * ih2 - 1.0f);
            float w = OMEGA_W * inv;
            float wi = w * ih2;
            ce = wi * cxe; cw = wi * cxw; cn = wi * cyn; cs = wi * cys;
            b = w * r3[idx];
        }
        ua[p] = uu; ae[p] = ce; aw[p] = cw; an[p] = cn; as_[p] = cs; bb[p] = b;
    }
    __syncthreads();

    // ---- 11 sweeps on the fixed interior [1,53)x[1,53)
    float* src = ua;
    float* dst = ub;
#pragma unroll 1
    for (int k = 0; k < L3H; ++k) {
#pragma unroll
        for (int r = 0; r < 4; ++r) {
            int ry = 1 + ty + 16 * r;
            if (ry < 53) {
                int base = ry * L3WS;
                {
                    int p = base + 1 + tx;
                    float um = src[p];
                    dst[p] = (1.0f - OMEGA_W) * um + bb[p] -
                             (ae[p] * src[p + 1] + aw[p] * src[p - 1] +
                              an[p] * src[p + L3WS] + as_[p] * src[p - L3WS]);
                }
                if (tx < 20) {
                    int p = base + 33 + tx;
                    float um = src[p];
                    dst[p] = (1.0f - OMEGA_W) * um + bb[p] -
                             (ae[p] * src[p + 1] + aw[p] * src[p - 1] +
                              an[p] * src[p + L3WS] + as_[p] * src[p - L3WS]);
                }
            }
        }
        __syncthreads();
        float* t = src; src = dst; dst = t;
    }

    // ---- store owned 32x32 (rows/cols [11,43))
    for (int q = tid; q < 1024; q += 512) {
        int py = L3H + (q >> 5), px = L3H + (q & 31);
        uout[(gy0 + py) * N3 + (gx0 + px)] = src[py * L3WS + px];
    }
}

// ---------------------------------------------------------------------------
// Host driver
// ---------------------------------------------------------------------------
extern "C" void kernel_launch(void* const* d_in, const int* in_sizes, int n_in,
                              void* d_out, int out_size) {
    const float* cx[4];
    const float* cy[4];
    const float* rhs;
    if (in_sizes[2] == in_sizes[0]) {
        for (int l = 0; l < 4; ++l) {
            cx[l] = (const float*)d_in[3 * l + 1];
            cy[l] = (const float*)d_in[3 * l + 2];
        }
        rhs = (const float*)d_in[12];
    } else {
        rhs = (const float*)d_in[0];
        for (int l = 0; l < 4; ++l) {
            cx[l] = (const float*)d_in[5 + l];
            cy[l] = (const float*)d_in[9 + l];
        }
    }

    float* uOUT = (float*)d_out;
    float *uB, *uC;
    float *u1a, *u1b, *r1;
    float *u2a, *u2b, *r2;
    float *u3a, *u3b, *r3;
    cudaGetSymbolAddress((void**)&uB, g_u0b);
    cudaGetSymbolAddress((void**)&uC, g_u0c);
    cudaGetSymbolAddress((void**)&u1a, g_u1a);
    cudaGetSymbolAddress((void**)&u1b, g_u1b);
    cudaGetSymbolAddress((void**)&r1, g_r1);
    cudaGetSymbolAddress((void**)&u2a, g_u2a);
    cudaGetSymbolAddress((void**)&u2b, g_u2b);
    cudaGetSymbolAddress((void**)&r2, g_r2);
    cudaGetSymbolAddress((void**)&u3a, g_u3a);
    cudaGetSymbolAddress((void**)&u3b, g_u3b);
    cudaGetSymbolAddress((void**)&r3, g_r3);

    const float ih2_0 = 1.0f, ih2_1 = 0.25f, ih2_2 = 0.0625f;

    dim3 blk(32, 8);
    dim3 t0(N0 / 64, N0 / 16);
    dim3 t1(N1 / 64, N1 / 16);
    dim3 t2(N2 / 64, N2 / 16);
    dim3 g3(8, 8), b3(32, 16);

    const int l3_smem = 7 * L3PTS * sizeof(float);  // 84,672 B
    cudaFuncSetAttribute(l3_sweeps_kernel,
                         cudaFuncAttributeMaxDynamicSharedMemorySize, l3_smem);

    for (int cyc = 0; cyc < 2; ++cyc) {
        // ----- level 0: pre-smooth (2) + residual + restrict -> r1; u -> uB
        if (cyc == 0) {
            jrr0_kernel<<<t0, blk>>>(rhs, cx[0], cy[0], uB, r1, N0, ih2_0);
        } else {
            jrr2_kernel<<<t0, blk>>>(uC, rhs, cx[0], cy[0], uB, r1, N0, ih2_0);
        }

        // ----- level 1: pre (from zero) + residual + restrict -> r2
        jrr0_kernel<<<t1, blk>>>(r1, cx[1], cy[1], u1a, r2, N1, ih2_1);

        // ----- level 2: pre (from zero) + residual + restrict -> r3
        jrr0_kernel<<<t2, blk>>>(r2, cx[2], cy[2], u2a, r3, N2, ih2_2);

        // ----- level 3: 22 sweeps = 2 launches of 11
        l3_sweeps_kernel<<<g3, b3, l3_smem>>>(u3a, r3, cx[3], cy[3], u3a, 1);
        l3_sweeps_kernel<<<g3, b3, l3_smem>>>(u3a, r3, cx[3], cy[3], u3b, 0);

        // ----- level 2: correct + post (2) -> e2 in u2b
        pjj_kernel<<<t2, blk>>>(u2a, u3b, r2, cx[2], cy[2], u2b, N2, ih2_2);

        // ----- level 1: correct + post (2) -> e1 in u1b
        pjj_kernel<<<t1, blk>>>(u1a, u2b, r1, cx[1], cy[1], u1b, N1, ih2_1);

        // ----- level 0: correct + post (2)
        if (cyc == 0) {
            pjj_kernel<<<t0, blk>>>(uB, u1b, rhs, cx[0], cy[0], uC, N0, ih2_0);
        } else {
            pjj_kernel<<<t0, blk>>>(uB, u1b, rhs, cx[0], cy[0], uOUT, N0, ih2_0);
        }
    }
}